// round 7
// baseline (speedup 1.0000x reference)
#include <cuda_runtime.h>
#include <cuda_fp16.h>
#include <cstdint>

// Fixed problem shape
#define BB   8
#define CC   256
#define HH   64
#define WWD  64
#define OO   256
#define KKT  9
#define HWSZ 4096

#define TP   128         // pixel tile per CTA
#define NT   512         // 16 warps: 4 M-warps (o) x 4 N-warps (px)
#define NITER 36         // 4 c-chunks of 64 x 9 kpos (kpos innermost -> L1 reuse)

// ---- smem layout (bytes) ----  total 123 KB -> ~100 KB L1 left for gather caching
#define SM_SI   0           // 9216
#define SM_SW   9216        // 18432 -> 27648
#define SM_A    27648       // 2 bufs x 32768 (256 o x 64 c fp16, SW128) -> 93184
#define SM_B    93184       // 2 bufs x 16384 (128 px x 64 c fp16, SW128) -> 125952
#define SMEM_TOTAL 125952

// ---- device scratch ----
__device__ __align__(16) __half g_wh[KKT * OO * CC];              // [k][o][c] fp16
__device__ __align__(16) __half g_xn[(size_t)BB * HWSZ * CC];     // NHWC fp16

// ---------------- prep kernels ----------------
__global__ void prep_weight(const float* __restrict__ w) {
    int o = blockIdx.x, k = blockIdx.y, c = threadIdx.x;
    float v = w[((size_t)o * CC + c) * KKT + k];
    g_wh[((size_t)k * OO + o) * CC + c] = __float2half_rn(v);
}

__global__ void prep_nhwc(const float* __restrict__ x) {
    __shared__ float tile[32][33];
    int bb = blockIdx.z, hw0 = blockIdx.x * 32, c0 = blockIdx.y * 32;
    int tx = threadIdx.x, ty = threadIdx.y;
    const float* src = x + (size_t)bb * CC * HWSZ;
    #pragma unroll
    for (int i = 0; i < 32; i += 8)
        tile[ty + i][tx] = src[(size_t)(c0 + ty + i) * HWSZ + hw0 + tx];
    __syncthreads();
    __half* dst = g_xn + (size_t)bb * HWSZ * CC;
    #pragma unroll
    for (int i = 0; i < 32; i += 8)
        dst[(size_t)(hw0 + ty + i) * CC + c0 + tx] = __float2half_rn(tile[tx][ty + i]);
}

// ---------------- helpers ----------------
__device__ __forceinline__ uint32_t s2u(const void* p) {
    uint32_t r;
    asm("{ .reg .u64 t; cvta.to.shared.u64 t, %1; cvt.u32.u64 %0, t; }" : "=r"(r) : "l"(p));
    return r;
}
__device__ __forceinline__ uint32_t sw128(uint32_t off) {
    return off ^ ((off >> 3) & 0x70);
}
__device__ __forceinline__ void ldsm_x4(uint32_t addr, uint32_t& r0, uint32_t& r1,
                                        uint32_t& r2, uint32_t& r3) {
    asm volatile("ldmatrix.sync.aligned.m8n8.x4.shared.b16 {%0,%1,%2,%3}, [%4];"
                 : "=r"(r0), "=r"(r1), "=r"(r2), "=r"(r3) : "r"(addr));
}
__device__ __forceinline__ void mma_fp16(float* d, const uint32_t* a, uint32_t b0, uint32_t b1) {
    asm volatile("mma.sync.aligned.m16n8k16.row.col.f32.f16.f16.f32 "
                 "{%0,%1,%2,%3}, {%4,%5,%6,%7}, {%8,%9}, {%0,%1,%2,%3};"
                 : "+f"(d[0]), "+f"(d[1]), "+f"(d[2]), "+f"(d[3])
                 : "r"(a[0]), "r"(a[1]), "r"(a[2]), "r"(a[3]), "r"(b0), "r"(b1));
}
__device__ __forceinline__ void cp16(uint32_t dst, const void* src) {
    asm volatile("cp.async.cg.shared.global [%0], [%1], 16;" :: "r"(dst), "l"(src) : "memory");
}
__device__ __forceinline__ void cp_commit() { asm volatile("cp.async.commit_group;" ::: "memory"); }
__device__ __forceinline__ void cp_wait0()  { asm volatile("cp.async.wait_group 0;"  ::: "memory"); }

extern __shared__ char smraw[];

__global__ __launch_bounds__(NT, 1)
void dcn_mma5_kernel(const float* __restrict__ offs,
                     const float* __restrict__ mask,
                     const float* __restrict__ bias,
                     float* __restrict__ out) {
    const int tid  = threadIdx.x;
    const int lane = tid & 31;
    const int wid  = tid >> 5;
    const int warpM = wid >> 2;        // 0..3 -> 64 o-rows
    const int warpN = wid & 3;         // 0..3 -> 32 px
    const int bb   = blockIdx.y;
    const int hw0  = blockIdx.x * TP;

    uint16_t* sI = (uint16_t*)(smraw + SM_SI);
    float*    sW = (float*)(smraw + SM_SW);
    const uint32_t uA = s2u(smraw + SM_A);
    const uint32_t uB = s2u(smraw + SM_B);

    // ---- taps: bilinear corner indices + mask-premultiplied weights ----
    for (int i = tid; i < KKT * TP; i += NT) {
        const int k  = i / TP;
        const int p  = i - k * TP;
        const int hw = hw0 + p;
        const int h  = hw >> 6;
        const int w  = hw & 63;

        const float oy = offs[((size_t)bb * 18 + k * 2 + 0) * HWSZ + hw];
        const float ox = offs[((size_t)bb * 18 + k * 2 + 1) * HWSZ + hw];
        const float m  = mask[((size_t)bb * KKT + k) * HWSZ + hw];

        const float py = (float)(h - 1 + k / 3) + oy;
        const float px = (float)(w - 1 + k % 3) + ox;
        const float fy = floorf(py), fx = floorf(px);
        const int y0 = (int)fy, x0 = (int)fx;
        const float ly = py - fy, lx = px - fx;
        const float hy = 1.0f - ly, hx = 1.0f - lx;

        const bool vy0 = (y0 >= 0) && (y0 < HH);
        const bool vy1 = (y0 + 1 >= 0) && (y0 + 1 < HH);
        const bool vx0 = (x0 >= 0) && (x0 < WWD);
        const bool vx1 = (x0 + 1 >= 0) && (x0 + 1 < WWD);
        const int cy0 = min(max(y0, 0), HH - 1);
        const int cy1 = min(max(y0 + 1, 0), HH - 1);
        const int cx0 = min(max(x0, 0), WWD - 1);
        const int cx1 = min(max(x0 + 1, 0), WWD - 1);

        sI[0 * 1152 + i] = (uint16_t)(cy0 * WWD + cx0);
        sI[1 * 1152 + i] = (uint16_t)(cy0 * WWD + cx1);
        sI[2 * 1152 + i] = (uint16_t)(cy1 * WWD + cx0);
        sI[3 * 1152 + i] = (uint16_t)(cy1 * WWD + cx1);
        sW[0 * 1152 + i] = (vy0 && vx0) ? hy * hx * m : 0.0f;
        sW[1 * 1152 + i] = (vy0 && vx1) ? hy * lx * m : 0.0f;
        sW[2 * 1152 + i] = (vy1 && vx0) ? ly * hx * m : 0.0f;
        sW[3 * 1152 + i] = (vy1 && vx1) ? ly * lx * m : 0.0f;
    }
    __syncthreads();

    const __half* __restrict__ xb = g_xn + (size_t)bb * HWSZ * CC;

    float acc[4][4][4];
    #pragma unroll
    for (int mf = 0; mf < 4; ++mf)
        #pragma unroll
        for (int nf = 0; nf < 4; ++nf)
            #pragma unroll
            for (int r = 0; r < 4; ++r) acc[mf][nf][r] = 0.0f;

    // ---- stage A: 256 o x 64 c fp16 (SW128 rows of 128B), via cp.async (L2-only) ----
    auto stageA = [&](int jt, int buf) {
        const int kpos = jt % KKT;
        const int c0   = (jt / KKT) * 64;
        const int q = tid & 7;          // 16B chunk within 128B row
        const int r = tid >> 3;         // 0..63
        const uint32_t abase = uA + buf * 32768;
        const uint32_t swoff = sw128((uint32_t)(r * 128 + q * 16));
        #pragma unroll
        for (int rr = 0; rr < 4; ++rr) {
            const int row = r + rr * 64;
            const __half* src = g_wh + ((size_t)kpos * OO + row) * CC + c0 + q * 8;
            cp16(abase + swoff + rr * 64 * 128, src);
        }
    };

    // gather regs: 2 px x 4 corners, 2 fp16 channels per lane (lane c = 2*lane)
    uint32_t g[2][4];
    auto loadQ = [&](int jt, int q) {
        const int kpos = jt % KKT;
        const int c0   = (jt / KKT) * 64;
        const __half* xc = xb + c0 + 2 * lane;
        #pragma unroll
        for (int e = 0; e < 2; ++e) {
            const int i = kpos * TP + wid * 8 + q * 2 + e;
            g[e][0] = *(const uint32_t*)(xc + (size_t)sI[0 * 1152 + i] * CC);
            g[e][1] = *(const uint32_t*)(xc + (size_t)sI[1 * 1152 + i] * CC);
            g[e][2] = *(const uint32_t*)(xc + (size_t)sI[2 * 1152 + i] * CC);
            g[e][3] = *(const uint32_t*)(xc + (size_t)sI[3 * 1152 + i] * CC);
        }
    };
    auto storeQ = [&](int jt, int q, int buf) {
        const int kpos = jt % KKT;
        char* Bb = smraw + SM_B + buf * 16384;
        #pragma unroll
        for (int e = 0; e < 2; ++e) {
            const int pp = wid * 8 + q * 2 + e;
            const int i  = kpos * TP + pp;
            const float w0 = sW[0 * 1152 + i], w1 = sW[1 * 1152 + i];
            const float w2 = sW[2 * 1152 + i], w3 = sW[3 * 1152 + i];
            float2 c0f = __half22float2(*(__half2*)&g[e][0]);
            float2 c1f = __half22float2(*(__half2*)&g[e][1]);
            float2 c2f = __half22float2(*(__half2*)&g[e][2]);
            float2 c3f = __half22float2(*(__half2*)&g[e][3]);
            float2 v;
            v.x = w0 * c0f.x + w1 * c1f.x + w2 * c2f.x + w3 * c3f.x;
            v.y = w0 * c0f.y + w1 * c1f.y + w2 * c2f.y + w3 * c3f.y;
            __half2 hv = __float22half2_rn(v);
            const uint32_t sw = sw128((uint32_t)(pp * 128 + lane * 4));
            *(uint32_t*)(Bb + sw) = *(uint32_t*)&hv;
        }
    };
    auto mmaKS = [&](int ks, int buf) {
        const uint32_t abase = uA + buf * 32768;
        const uint32_t bbase = uB + buf * 16384;
        uint32_t a[4][4];
        #pragma unroll
        for (int mf = 0; mf < 4; ++mf) {
            const uint32_t off = (uint32_t)((warpM * 64 + mf * 16 + (lane & 15)) * 128
                                            + ks * 32 + (lane >> 4) * 16);
            ldsm_x4(abase + sw128(off), a[mf][0], a[mf][1], a[mf][2], a[mf][3]);
        }
        uint32_t bfr[4][2];
        #pragma unroll
        for (int pb = 0; pb < 2; ++pb) {
            const uint32_t off = (uint32_t)((warpN * 32 + pb * 16 + (lane & 15)) * 128
                                            + ks * 32 + (lane >> 4) * 16);
            uint32_t r0, r1, r2, r3;
            ldsm_x4(bbase + sw128(off), r0, r1, r2, r3);
            bfr[pb * 2 + 0][0] = r0; bfr[pb * 2 + 0][1] = r2;
            bfr[pb * 2 + 1][0] = r1; bfr[pb * 2 + 1][1] = r3;
        }
        #pragma unroll
        for (int mf = 0; mf < 4; ++mf)
            #pragma unroll
            for (int nf = 0; nf < 4; ++nf)
                mma_fp16(acc[mf][nf], a[mf], bfr[nf][0], bfr[nf][1]);
    };

    // ---- prologue: build iteration 0 into buffer 0 ----
    stageA(0, 0);
    cp_commit();
    #pragma unroll
    for (int q = 0; q < 4; ++q) { loadQ(0, q); storeQ(0, q, 0); }
    cp_wait0();
    __syncthreads();

    // ---- main loop: one sync per iter; build(it+1) woven into MMA(it) ----
    for (int it = 0; it < NITER; ++it) {
        const int buf = it & 1;
        const bool more = (it + 1 < NITER);
        if (more) { stageA(it + 1, buf ^ 1); cp_commit(); }

        if (more) loadQ(it + 1, 0);
        mmaKS(0, buf);
        if (more) { storeQ(it + 1, 0, buf ^ 1); loadQ(it + 1, 1); }
        mmaKS(1, buf);
        if (more) { storeQ(it + 1, 1, buf ^ 1); loadQ(it + 1, 2); }
        mmaKS(2, buf);
        if (more) { storeQ(it + 1, 2, buf ^ 1); loadQ(it + 1, 3); }
        mmaKS(3, buf);
        if (more) storeQ(it + 1, 3, buf ^ 1);

        cp_wait0();
        __syncthreads();
    }

    // ---- epilogue: bias add + fp32 stores ----
    #pragma unroll
    for (int mf = 0; mf < 4; ++mf) {
        const int o0 = warpM * 64 + mf * 16 + (lane >> 2);
        const float bv0 = bias[o0];
        const float bv1 = bias[o0 + 8];
        #pragma unroll
        for (int nf = 0; nf < 4; ++nf) {
            const int p = hw0 + warpN * 32 + nf * 8 + (lane & 3) * 2;
            float* d0 = out + ((size_t)(bb * OO + o0)) * HWSZ + p;
            float* d1 = out + ((size_t)(bb * OO + o0 + 8)) * HWSZ + p;
            float2 v0, v1;
            v0.x = acc[mf][nf][0] + bv0; v0.y = acc[mf][nf][1] + bv0;
            v1.x = acc[mf][nf][2] + bv1; v1.y = acc[mf][nf][3] + bv1;
            *(float2*)d0 = v0;
            *(float2*)d1 = v1;
        }
    }
}

extern "C" void kernel_launch(void* const* d_in, const int* in_sizes, int n_in,
                              void* d_out, int out_size) {
    const float* inp    = (const float*)d_in[0];  // [8,256,64,64]
    const float* offs   = (const float*)d_in[1];  // [8,18,64,64]
    const float* mask   = (const float*)d_in[2];  // [8,9,64,64]
    const float* weight = (const float*)d_in[3];  // [256,256,3,3]
    const float* bias   = (const float*)d_in[4];  // [256]
    float* out = (float*)d_out;                   // [8,256,64,64]

    cudaFuncSetAttribute(dcn_mma5_kernel,
                         cudaFuncAttributeMaxDynamicSharedMemorySize, SMEM_TOTAL);

    prep_weight<<<dim3(OO, KKT), CC>>>(weight);
    prep_nhwc<<<dim3(HWSZ / 32, CC / 32, BB), dim3(32, 8)>>>(inp);

    dim3 grid(HWSZ / TP, BB);   // (32, 8) = 256 CTAs
    dcn_mma5_kernel<<<grid, NT, SMEM_TOTAL>>>(offs, mask, bias, out);
}

// round 8
// speedup vs baseline: 1.1000x; 1.1000x over previous
#include <cuda_runtime.h>
#include <cuda_fp16.h>
#include <cstdint>

// Fixed problem shape
#define BB   8
#define CC   256
#define HH   64
#define WWD  64
#define OO   256
#define KKT  9
#define HWSZ 4096

#define TP   128         // pixel tile per CTA
#define NT   512         // 16 warps: 4 M-warps (o) x 4 N-warps (px)
#define NITER 18         // 2 c-chunks of 128 x 9 kpos (kpos innermost)

// ---- smem layout (bytes) ----
#define SM_SI   0
#define SM_SW   9216
#define SM_A    27648       // 2 bufs x 65536 (256 o x 128 c fp16, two SW128 half-planes)
#define SM_B    158720      // 2 bufs x 32768 (128 px x 128 c fp16, two SW128 half-planes)
#define SMEM_TOTAL 224256

// ---- device scratch ----
__device__ __align__(16) __half g_wh[KKT * OO * CC];              // [k][o][c] fp16
__device__ __align__(16) __half g_xn[(size_t)BB * HWSZ * CC];     // NHWC fp16

// ---------------- prep kernels ----------------
__global__ void prep_weight(const float* __restrict__ w) {
    int o = blockIdx.x, k = blockIdx.y, c = threadIdx.x;
    float v = w[((size_t)o * CC + c) * KKT + k];
    g_wh[((size_t)k * OO + o) * CC + c] = __float2half_rn(v);
}

__global__ void prep_nhwc(const float* __restrict__ x) {
    __shared__ float tile[32][33];
    int bb = blockIdx.z, hw0 = blockIdx.x * 32, c0 = blockIdx.y * 32;
    int tx = threadIdx.x, ty = threadIdx.y;
    const float* src = x + (size_t)bb * CC * HWSZ;
    #pragma unroll
    for (int i = 0; i < 32; i += 8)
        tile[ty + i][tx] = src[(size_t)(c0 + ty + i) * HWSZ + hw0 + tx];
    __syncthreads();
    __half* dst = g_xn + (size_t)bb * HWSZ * CC;
    #pragma unroll
    for (int i = 0; i < 32; i += 8)
        dst[(size_t)(hw0 + ty + i) * CC + c0 + tx] = __float2half_rn(tile[tx][ty + i]);
}

// ---------------- helpers ----------------
__device__ __forceinline__ uint32_t s2u(const void* p) {
    uint32_t r;
    asm("{ .reg .u64 t; cvta.to.shared.u64 t, %1; cvt.u32.u64 %0, t; }" : "=r"(r) : "l"(p));
    return r;
}
__device__ __forceinline__ uint32_t sw128(uint32_t off) {
    return off ^ ((off >> 3) & 0x70);
}
__device__ __forceinline__ void ldsm_x4(uint32_t addr, uint32_t& r0, uint32_t& r1,
                                        uint32_t& r2, uint32_t& r3) {
    asm volatile("ldmatrix.sync.aligned.m8n8.x4.shared.b16 {%0,%1,%2,%3}, [%4];"
                 : "=r"(r0), "=r"(r1), "=r"(r2), "=r"(r3) : "r"(addr));
}
__device__ __forceinline__ void mma_fp16(float* d, const uint32_t* a, uint32_t b0, uint32_t b1) {
    asm volatile("mma.sync.aligned.m16n8k16.row.col.f32.f16.f16.f32 "
                 "{%0,%1,%2,%3}, {%4,%5,%6,%7}, {%8,%9}, {%0,%1,%2,%3};"
                 : "+f"(d[0]), "+f"(d[1]), "+f"(d[2]), "+f"(d[3])
                 : "r"(a[0]), "r"(a[1]), "r"(a[2]), "r"(a[3]), "r"(b0), "r"(b1));
}
__device__ __forceinline__ void cp16(uint32_t dst, const void* src) {
    asm volatile("cp.async.cg.shared.global [%0], [%1], 16;" :: "r"(dst), "l"(src) : "memory");
}
__device__ __forceinline__ void cp_commit() { asm volatile("cp.async.commit_group;" ::: "memory"); }
__device__ __forceinline__ void cp_wait0()  { asm volatile("cp.async.wait_group 0;"  ::: "memory"); }

extern __shared__ char smraw[];

__global__ __launch_bounds__(NT, 1)
void dcn_mma6_kernel(const float* __restrict__ offs,
                     const float* __restrict__ mask,
                     const float* __restrict__ bias,
                     float* __restrict__ out) {
    const int tid  = threadIdx.x;
    const int lane = tid & 31;
    const int wid  = tid >> 5;
    const int warpM = wid >> 2;        // 0..3 -> 64 o-rows
    const int warpN = wid & 3;         // 0..3 -> 32 px
    const int bb   = blockIdx.y;
    const int hw0  = blockIdx.x * TP;

    uint16_t* sI = (uint16_t*)(smraw + SM_SI);
    float*    sW = (float*)(smraw + SM_SW);
    const uint32_t uA = s2u(smraw + SM_A);
    const uint32_t uB = s2u(smraw + SM_B);

    // ---- taps: bilinear corner indices + mask-premultiplied weights ----
    for (int i = tid; i < KKT * TP; i += NT) {
        const int k  = i / TP;
        const int p  = i - k * TP;
        const int hw = hw0 + p;
        const int h  = hw >> 6;
        const int w  = hw & 63;

        const float oy = offs[((size_t)bb * 18 + k * 2 + 0) * HWSZ + hw];
        const float ox = offs[((size_t)bb * 18 + k * 2 + 1) * HWSZ + hw];
        const float m  = mask[((size_t)bb * KKT + k) * HWSZ + hw];

        const float py = (float)(h - 1 + k / 3) + oy;
        const float px = (float)(w - 1 + k % 3) + ox;
        const float fy = floorf(py), fx = floorf(px);
        const int y0 = (int)fy, x0 = (int)fx;
        const float ly = py - fy, lx = px - fx;
        const float hy = 1.0f - ly, hx = 1.0f - lx;

        const bool vy0 = (y0 >= 0) && (y0 < HH);
        const bool vy1 = (y0 + 1 >= 0) && (y0 + 1 < HH);
        const bool vx0 = (x0 >= 0) && (x0 < WWD);
        const bool vx1 = (x0 + 1 >= 0) && (x0 + 1 < WWD);
        const int cy0 = min(max(y0, 0), HH - 1);
        const int cy1 = min(max(y0 + 1, 0), HH - 1);
        const int cx0 = min(max(x0, 0), WWD - 1);
        const int cx1 = min(max(x0 + 1, 0), WWD - 1);

        sI[0 * 1152 + i] = (uint16_t)(cy0 * WWD + cx0);
        sI[1 * 1152 + i] = (uint16_t)(cy0 * WWD + cx1);
        sI[2 * 1152 + i] = (uint16_t)(cy1 * WWD + cx0);
        sI[3 * 1152 + i] = (uint16_t)(cy1 * WWD + cx1);
        sW[0 * 1152 + i] = (vy0 && vx0) ? hy * hx * m : 0.0f;
        sW[1 * 1152 + i] = (vy0 && vx1) ? hy * lx * m : 0.0f;
        sW[2 * 1152 + i] = (vy1 && vx0) ? ly * hx * m : 0.0f;
        sW[3 * 1152 + i] = (vy1 && vx1) ? ly * lx * m : 0.0f;
    }
    __syncthreads();

    const __half* __restrict__ xb = g_xn + (size_t)bb * HWSZ * CC;

    float acc[4][4][4];
    #pragma unroll
    for (int mf = 0; mf < 4; ++mf)
        #pragma unroll
        for (int nf = 0; nf < 4; ++nf)
            #pragma unroll
            for (int r = 0; r < 4; ++r) acc[mf][nf][r] = 0.0f;

    // ---- stage A: 256 o x 128 c fp16 as two SW128 half-planes, via cp.async ----
    auto stageA = [&](int jt, int buf) {
        const int kpos = jt % KKT;
        const int c0   = (jt / KKT) * 128;
        const int q = tid & 7;          // 16B chunk within 128B row
        const int r = tid >> 3;         // 0..63
        const uint32_t abase = uA + buf * 65536;
        const uint32_t swoff = sw128((uint32_t)(r * 128 + q * 16));
        #pragma unroll
        for (int rr = 0; rr < 4; ++rr) {
            const int row = r + rr * 64;
            const __half* src = g_wh + ((size_t)kpos * OO + row) * CC + c0 + q * 8;
            cp16(abase + swoff + rr * 64 * 128, src);              // half-plane 0
            cp16(abase + 32768 + swoff + rr * 64 * 128, src + 64); // half-plane 1
        }
    };

    // Per-pixel gather pipeline: 2 slots x 4 corners x uint2 (4 fp16 ch / lane)
    uint2 g[2][4];
    auto loadP = [&](int jt, int p, int s) {
        const int kpos = jt % KKT;
        const int c0   = (jt / KKT) * 128;
        const __half* xc = xb + c0 + 4 * lane;
        const int i = kpos * TP + wid * 8 + p;
        g[s][0] = *(const uint2*)(xc + (size_t)sI[0 * 1152 + i] * CC);
        g[s][1] = *(const uint2*)(xc + (size_t)sI[1 * 1152 + i] * CC);
        g[s][2] = *(const uint2*)(xc + (size_t)sI[2 * 1152 + i] * CC);
        g[s][3] = *(const uint2*)(xc + (size_t)sI[3 * 1152 + i] * CC);
    };
    auto storeP = [&](int jt, int p, int s, int buf) {
        const int kpos = jt % KKT;
        char* Bb = smraw + SM_B + buf * 32768 + (lane >> 4) * 16384;
        const int pp = wid * 8 + p;
        const int i  = kpos * TP + pp;
        const float w0 = sW[0 * 1152 + i], w1 = sW[1 * 1152 + i];
        const float w2 = sW[2 * 1152 + i], w3 = sW[3 * 1152 + i];
        float2 c0a = __half22float2(*(__half2*)&g[s][0].x);
        float2 c0b = __half22float2(*(__half2*)&g[s][0].y);
        float2 c1a = __half22float2(*(__half2*)&g[s][1].x);
        float2 c1b = __half22float2(*(__half2*)&g[s][1].y);
        float2 c2a = __half22float2(*(__half2*)&g[s][2].x);
        float2 c2b = __half22float2(*(__half2*)&g[s][2].y);
        float2 c3a = __half22float2(*(__half2*)&g[s][3].x);
        float2 c3b = __half22float2(*(__half2*)&g[s][3].y);
        float2 va, vb;
        va.x = w0 * c0a.x + w1 * c1a.x + w2 * c2a.x + w3 * c3a.x;
        va.y = w0 * c0a.y + w1 * c1a.y + w2 * c2a.y + w3 * c3a.y;
        vb.x = w0 * c0b.x + w1 * c1b.x + w2 * c2b.x + w3 * c3b.x;
        vb.y = w0 * c0b.y + w1 * c1b.y + w2 * c2b.y + w3 * c3b.y;
        __half2 h01 = __float22half2_rn(va);
        __half2 h23 = __float22half2_rn(vb);
        uint2 pk;
        pk.x = *(uint32_t*)&h01;
        pk.y = *(uint32_t*)&h23;
        *(uint2*)(Bb + sw128((uint32_t)(pp * 128 + (lane & 15) * 8))) = pk;
    };
    auto mmaKS = [&](int ks, int buf) {
        const int half = ks >> 2;
        const int ksl  = ks & 3;
        const uint32_t abase = uA + buf * 65536 + half * 32768;
        const uint32_t bbase = uB + buf * 32768 + half * 16384;
        uint32_t a[4][4];
        #pragma unroll
        for (int mf = 0; mf < 4; ++mf) {
            const uint32_t off = (uint32_t)((warpM * 64 + mf * 16 + (lane & 15)) * 128
                                            + ksl * 32 + (lane >> 4) * 16);
            ldsm_x4(abase + sw128(off), a[mf][0], a[mf][1], a[mf][2], a[mf][3]);
        }
        uint32_t bfr[4][2];
        #pragma unroll
        for (int pb = 0; pb < 2; ++pb) {
            const uint32_t off = (uint32_t)((warpN * 32 + pb * 16 + (lane & 15)) * 128
                                            + ksl * 32 + (lane >> 4) * 16);
            uint32_t r0, r1, r2, r3;
            ldsm_x4(bbase + sw128(off), r0, r1, r2, r3);
            bfr[pb * 2 + 0][0] = r0; bfr[pb * 2 + 0][1] = r2;
            bfr[pb * 2 + 1][0] = r1; bfr[pb * 2 + 1][1] = r3;
        }
        #pragma unroll
        for (int mf = 0; mf < 4; ++mf)
            #pragma unroll
            for (int nf = 0; nf < 4; ++nf)
                mma_fp16(acc[mf][nf], a[mf], bfr[nf][0], bfr[nf][1]);
    };

    // ---- prologue: build iteration 0 into buffer 0 ----
    stageA(0, 0);
    cp_commit();
    #pragma unroll
    for (int p = 0; p < 8; ++p) { loadP(0, p, p & 1); storeP(0, p, p & 1, 0); }
    cp_wait0();
    __syncthreads();

    // ---- main loop: one sync per iter; per-pixel gather pipeline (lead = 2 mmaKS) ----
    for (int it = 0; it < NITER; ++it) {
        const int buf  = it & 1;
        const int nbuf = buf ^ 1;
        const bool more = (it + 1 < NITER);
        if (more) { stageA(it + 1, nbuf); cp_commit(); }
        if (more) { loadP(it + 1, 0, 0); loadP(it + 1, 1, 1); }

        #pragma unroll
        for (int j = 0; j < 8; ++j) {
            mmaKS(j, buf);
            if (more) {
                storeP(it + 1, j, j & 1, nbuf);
                if (j < 6) loadP(it + 1, j + 2, j & 1);
            }
        }

        cp_wait0();
        __syncthreads();
    }

    // ---- epilogue: bias add + fp32 stores ----
    #pragma unroll
    for (int mf = 0; mf < 4; ++mf) {
        const int o0 = warpM * 64 + mf * 16 + (lane >> 2);
        const float bv0 = bias[o0];
        const float bv1 = bias[o0 + 8];
        #pragma unroll
        for (int nf = 0; nf < 4; ++nf) {
            const int p = hw0 + warpN * 32 + nf * 8 + (lane & 3) * 2;
            float* d0 = out + ((size_t)(bb * OO + o0)) * HWSZ + p;
            float* d1 = out + ((size_t)(bb * OO + o0 + 8)) * HWSZ + p;
            float2 v0, v1;
            v0.x = acc[mf][nf][0] + bv0; v0.y = acc[mf][nf][1] + bv0;
            v1.x = acc[mf][nf][2] + bv1; v1.y = acc[mf][nf][3] + bv1;
            *(float2*)d0 = v0;
            *(float2*)d1 = v1;
        }
    }
}

extern "C" void kernel_launch(void* const* d_in, const int* in_sizes, int n_in,
                              void* d_out, int out_size) {
    const float* inp    = (const float*)d_in[0];  // [8,256,64,64]
    const float* offs   = (const float*)d_in[1];  // [8,18,64,64]
    const float* mask   = (const float*)d_in[2];  // [8,9,64,64]
    const float* weight = (const float*)d_in[3];  // [256,256,3,3]
    const float* bias   = (const float*)d_in[4];  // [256]
    float* out = (float*)d_out;                   // [8,256,64,64]

    cudaFuncSetAttribute(dcn_mma6_kernel,
                         cudaFuncAttributeMaxDynamicSharedMemorySize, SMEM_TOTAL);

    prep_weight<<<dim3(OO, KKT), CC>>>(weight);
    prep_nhwc<<<dim3(HWSZ / 32, CC / 32, BB), dim3(32, 8)>>>(inp);

    dim3 grid(HWSZ / TP, BB);   // (32, 8) = 256 CTAs
    dcn_mma6_kernel<<<grid, NT, SMEM_TOTAL>>>(offs, mask, bias, out);
}

// round 9
// speedup vs baseline: 1.1878x; 1.0799x over previous
#include <cuda_runtime.h>
#include <cuda_fp16.h>
#include <cstdint>

// Fixed problem shape
#define BB   8
#define CC   256
#define HH   64
#define WWD  64
#define OO   256
#define KKT  9
#define HWSZ 4096

#define TP   128         // pixel tile per CTA
#define NT   512         // 16 warps: 4 M-warps (o) x 4 N-warps (px)
#define NITER 18         // 2 c-chunks of 128 x 9 kpos (kpos innermost)

// ---- smem layout (bytes) ----
#define SM_T    0           // taps: 1152 x 16B = 18432
#define SM_A    18432       // 2 bufs x 65536 (256 o x 128 c fp16, two SW128 half-planes) -> 149504
#define SM_B    149504      // 2 bufs x 32768 (128 px x 128 c fp16, two SW128 half-planes) -> 215040
#define SMEM_TOTAL 215040

// Packed bilinear tap: 4 corner indices + 4 fp16 weights (mask-premultiplied)
struct __align__(16) Tap {
    unsigned short idx[4];
    __half2 w01;
    __half2 w23;
};

// ---- device scratch ----
__device__ __align__(16) __half g_wh[KKT * OO * CC];              // [k][o][c] fp16
__device__ __align__(16) __half g_xn[(size_t)BB * HWSZ * CC];     // NHWC fp16

// ---------------- prep kernels ----------------
__global__ void prep_weight(const float* __restrict__ w) {
    int o = blockIdx.x, k = blockIdx.y, c = threadIdx.x;
    float v = w[((size_t)o * CC + c) * KKT + k];
    g_wh[((size_t)k * OO + o) * CC + c] = __float2half_rn(v);
}

__global__ void prep_nhwc(const float* __restrict__ x) {
    __shared__ float tile[32][33];
    int bb = blockIdx.z, hw0 = blockIdx.x * 32, c0 = blockIdx.y * 32;
    int tx = threadIdx.x, ty = threadIdx.y;
    const float* src = x + (size_t)bb * CC * HWSZ;
    #pragma unroll
    for (int i = 0; i < 32; i += 8)
        tile[ty + i][tx] = src[(size_t)(c0 + ty + i) * HWSZ + hw0 + tx];
    __syncthreads();
    __half* dst = g_xn + (size_t)bb * HWSZ * CC;
    #pragma unroll
    for (int i = 0; i < 32; i += 8)
        dst[(size_t)(hw0 + ty + i) * CC + c0 + tx] = __float2half_rn(tile[tx][ty + i]);
}

// ---------------- helpers ----------------
__device__ __forceinline__ uint32_t s2u(const void* p) {
    uint32_t r;
    asm("{ .reg .u64 t; cvta.to.shared.u64 t, %1; cvt.u32.u64 %0, t; }" : "=r"(r) : "l"(p));
    return r;
}
__device__ __forceinline__ uint32_t sw128(uint32_t off) {
    return off ^ ((off >> 3) & 0x70);
}
__device__ __forceinline__ void ldsm_x4(uint32_t addr, uint32_t& r0, uint32_t& r1,
                                        uint32_t& r2, uint32_t& r3) {
    asm volatile("ldmatrix.sync.aligned.m8n8.x4.shared.b16 {%0,%1,%2,%3}, [%4];"
                 : "=r"(r0), "=r"(r1), "=r"(r2), "=r"(r3) : "r"(addr));
}
__device__ __forceinline__ void mma_fp16(float* d, const uint32_t* a, uint32_t b0, uint32_t b1) {
    asm volatile("mma.sync.aligned.m16n8k16.row.col.f32.f16.f16.f32 "
                 "{%0,%1,%2,%3}, {%4,%5,%6,%7}, {%8,%9}, {%0,%1,%2,%3};"
                 : "+f"(d[0]), "+f"(d[1]), "+f"(d[2]), "+f"(d[3])
                 : "r"(a[0]), "r"(a[1]), "r"(a[2]), "r"(a[3]), "r"(b0), "r"(b1));
}
__device__ __forceinline__ void cp16(uint32_t dst, const void* src) {
    asm volatile("cp.async.cg.shared.global [%0], [%1], 16;" :: "r"(dst), "l"(src) : "memory");
}
__device__ __forceinline__ void cp_commit() { asm volatile("cp.async.commit_group;" ::: "memory"); }
__device__ __forceinline__ void cp_wait0()  { asm volatile("cp.async.wait_group 0;"  ::: "memory"); }

extern __shared__ char smraw[];

__global__ __launch_bounds__(NT, 1)
void dcn_mma7_kernel(const float* __restrict__ offs,
                     const float* __restrict__ mask,
                     const float* __restrict__ bias,
                     float* __restrict__ out) {
    const int tid  = threadIdx.x;
    const int lane = tid & 31;
    const int wid  = tid >> 5;
    const int warpM = wid >> 2;        // 0..3 -> 64 o-rows
    const int warpN = wid & 3;         // 0..3 -> 32 px
    const int bb   = blockIdx.y;
    const int hw0  = blockIdx.x * TP;

    Tap* sT = (Tap*)(smraw + SM_T);
    const uint32_t uA = s2u(smraw + SM_A);
    const uint32_t uB = s2u(smraw + SM_B);

    // ---- taps: bilinear corner indices + mask-premultiplied fp16 weights ----
    for (int i = tid; i < KKT * TP; i += NT) {
        const int k  = i / TP;
        const int p  = i - k * TP;
        const int hw = hw0 + p;
        const int h  = hw >> 6;
        const int w  = hw & 63;

        const float oy = offs[((size_t)bb * 18 + k * 2 + 0) * HWSZ + hw];
        const float ox = offs[((size_t)bb * 18 + k * 2 + 1) * HWSZ + hw];
        const float m  = mask[((size_t)bb * KKT + k) * HWSZ + hw];

        const float py = (float)(h - 1 + k / 3) + oy;
        const float px = (float)(w - 1 + k % 3) + ox;
        const float fy = floorf(py), fx = floorf(px);
        const int y0 = (int)fy, x0 = (int)fx;
        const float ly = py - fy, lx = px - fx;
        const float hy = 1.0f - ly, hx = 1.0f - lx;

        const bool vy0 = (y0 >= 0) && (y0 < HH);
        const bool vy1 = (y0 + 1 >= 0) && (y0 + 1 < HH);
        const bool vx0 = (x0 >= 0) && (x0 < WWD);
        const bool vx1 = (x0 + 1 >= 0) && (x0 + 1 < WWD);
        const int cy0 = min(max(y0, 0), HH - 1);
        const int cy1 = min(max(y0 + 1, 0), HH - 1);
        const int cx0 = min(max(x0, 0), WWD - 1);
        const int cx1 = min(max(x0 + 1, 0), WWD - 1);

        Tap t;
        t.idx[0] = (unsigned short)(cy0 * WWD + cx0);
        t.idx[1] = (unsigned short)(cy0 * WWD + cx1);
        t.idx[2] = (unsigned short)(cy1 * WWD + cx0);
        t.idx[3] = (unsigned short)(cy1 * WWD + cx1);
        const float w0v = (vy0 && vx0) ? hy * hx * m : 0.0f;
        const float w1v = (vy0 && vx1) ? hy * lx * m : 0.0f;
        const float w2v = (vy1 && vx0) ? ly * hx * m : 0.0f;
        const float w3v = (vy1 && vx1) ? ly * lx * m : 0.0f;
        t.w01 = __floats2half2_rn(w0v, w1v);
        t.w23 = __floats2half2_rn(w2v, w3v);
        sT[i] = t;
    }
    __syncthreads();

    const __half* __restrict__ xb = g_xn + (size_t)bb * HWSZ * CC;

    float acc[4][4][4];
    #pragma unroll
    for (int mf = 0; mf < 4; ++mf)
        #pragma unroll
        for (int nf = 0; nf < 4; ++nf)
            #pragma unroll
            for (int r = 0; r < 4; ++r) acc[mf][nf][r] = 0.0f;

    // ---- stage A: 256 o x 128 c fp16 as two SW128 half-planes, via cp.async ----
    auto stageA = [&](int jt, int buf) {
        const int kpos = jt % KKT;
        const int c0   = (jt / KKT) * 128;
        const int q = tid & 7;          // 16B chunk within 128B row
        const int r = tid >> 3;         // 0..63
        const uint32_t abase = uA + buf * 65536;
        const uint32_t swoff = sw128((uint32_t)(r * 128 + q * 16));
        #pragma unroll
        for (int rr = 0; rr < 4; ++rr) {
            const int row = r + rr * 64;
            const __half* src = g_wh + ((size_t)kpos * OO + row) * CC + c0 + q * 8;
            cp16(abase + swoff + rr * 64 * 128, src);              // half-plane 0
            cp16(abase + 32768 + swoff + rr * 64 * 128, src + 64); // half-plane 1
        }
    };

    // Per-pixel gather pipeline: 2 slots x (4 corners uint2 + packed weights)
    uint2   g[2][4];
    __half2 wA[2], wB[2];   // w01, w23 per slot
    auto loadP = [&](int jt, int p, int s) {
        const int kpos = jt % KKT;
        const int c0   = (jt / KKT) * 128;
        const __half* xc = xb + c0 + 4 * lane;
        const Tap t = sT[kpos * TP + wid * 8 + p];   // single LDS.128
        g[s][0] = *(const uint2*)(xc + (size_t)t.idx[0] * CC);
        g[s][1] = *(const uint2*)(xc + (size_t)t.idx[1] * CC);
        g[s][2] = *(const uint2*)(xc + (size_t)t.idx[2] * CC);
        g[s][3] = *(const uint2*)(xc + (size_t)t.idx[3] * CC);
        wA[s] = t.w01;
        wB[s] = t.w23;
    };
    auto storeP = [&](int p, int s, int buf) {
        char* Bb = smraw + SM_B + buf * 32768 + (lane >> 4) * 16384;
        const int pp = wid * 8 + p;
        const __half2 h0 = __low2half2(wA[s]);
        const __half2 h1 = __high2half2(wA[s]);
        const __half2 h2 = __low2half2(wB[s]);
        const __half2 h3 = __high2half2(wB[s]);
        // channels 0,1
        __half2 vA = __hmul2(h0, *(__half2*)&g[s][0].x);
        vA = __hfma2(h1, *(__half2*)&g[s][1].x, vA);
        vA = __hfma2(h2, *(__half2*)&g[s][2].x, vA);
        vA = __hfma2(h3, *(__half2*)&g[s][3].x, vA);
        // channels 2,3
        __half2 vB = __hmul2(h0, *(__half2*)&g[s][0].y);
        vB = __hfma2(h1, *(__half2*)&g[s][1].y, vB);
        vB = __hfma2(h2, *(__half2*)&g[s][2].y, vB);
        vB = __hfma2(h3, *(__half2*)&g[s][3].y, vB);
        uint2 pk;
        pk.x = *(uint32_t*)&vA;
        pk.y = *(uint32_t*)&vB;
        *(uint2*)(Bb + sw128((uint32_t)(pp * 128 + (lane & 15) * 8))) = pk;
    };
    auto mmaKS = [&](int ks, int buf) {
        const int half = ks >> 2;
        const int ksl  = ks & 3;
        const uint32_t abase = uA + buf * 65536 + half * 32768;
        const uint32_t bbase = uB + buf * 32768 + half * 16384;
        uint32_t a[4][4];
        #pragma unroll
        for (int mf = 0; mf < 4; ++mf) {
            const uint32_t off = (uint32_t)((warpM * 64 + mf * 16 + (lane & 15)) * 128
                                            + ksl * 32 + (lane >> 4) * 16);
            ldsm_x4(abase + sw128(off), a[mf][0], a[mf][1], a[mf][2], a[mf][3]);
        }
        uint32_t bfr[4][2];
        #pragma unroll
        for (int pb = 0; pb < 2; ++pb) {
            const uint32_t off = (uint32_t)((warpN * 32 + pb * 16 + (lane & 15)) * 128
                                            + ksl * 32 + (lane >> 4) * 16);
            uint32_t r0, r1, r2, r3;
            ldsm_x4(bbase + sw128(off), r0, r1, r2, r3);
            bfr[pb * 2 + 0][0] = r0; bfr[pb * 2 + 0][1] = r2;
            bfr[pb * 2 + 1][0] = r1; bfr[pb * 2 + 1][1] = r3;
        }
        #pragma unroll
        for (int mf = 0; mf < 4; ++mf)
            #pragma unroll
            for (int nf = 0; nf < 4; ++nf)
                mma_fp16(acc[mf][nf], a[mf], bfr[nf][0], bfr[nf][1]);
    };

    // ---- prologue: build iteration 0 into buffer 0 ----
    stageA(0, 0);
    cp_commit();
    #pragma unroll
    for (int p = 0; p < 8; ++p) { loadP(0, p, p & 1); storeP(p, p & 1, 0); }
    cp_wait0();
    __syncthreads();

    // ---- main loop: one sync per iter; per-pixel gather pipeline (lead = 2 mmaKS) ----
    for (int it = 0; it < NITER; ++it) {
        const int buf  = it & 1;
        const int nbuf = buf ^ 1;
        const bool more = (it + 1 < NITER);
        if (more) { stageA(it + 1, nbuf); cp_commit(); }
        if (more) { loadP(it + 1, 0, 0); loadP(it + 1, 1, 1); }

        #pragma unroll
        for (int j = 0; j < 8; ++j) {
            mmaKS(j, buf);
            if (more) {
                storeP(j, j & 1, nbuf);
                if (j < 6) loadP(it + 1, j + 2, j & 1);
            }
        }

        cp_wait0();
        __syncthreads();
    }

    // ---- epilogue: bias add + fp32 stores ----
    #pragma unroll
    for (int mf = 0; mf < 4; ++mf) {
        const int o0 = warpM * 64 + mf * 16 + (lane >> 2);
        const float bv0 = bias[o0];
        const float bv1 = bias[o0 + 8];
        #pragma unroll
        for (int nf = 0; nf < 4; ++nf) {
            const int p = hw0 + warpN * 32 + nf * 8 + (lane & 3) * 2;
            float* d0 = out + ((size_t)(bb * OO + o0)) * HWSZ + p;
            float* d1 = out + ((size_t)(bb * OO + o0 + 8)) * HWSZ + p;
            float2 v0, v1;
            v0.x = acc[mf][nf][0] + bv0; v0.y = acc[mf][nf][1] + bv0;
            v1.x = acc[mf][nf][2] + bv1; v1.y = acc[mf][nf][3] + bv1;
            *(float2*)d0 = v0;
            *(float2*)d1 = v1;
        }
    }
}

extern "C" void kernel_launch(void* const* d_in, const int* in_sizes, int n_in,
                              void* d_out, int out_size) {
    const float* inp    = (const float*)d_in[0];  // [8,256,64,64]
    const float* offs   = (const float*)d_in[1];  // [8,18,64,64]
    const float* mask   = (const float*)d_in[2];  // [8,9,64,64]
    const float* weight = (const float*)d_in[3];  // [256,256,3,3]
    const float* bias   = (const float*)d_in[4];  // [256]
    float* out = (float*)d_out;                   // [8,256,64,64]

    cudaFuncSetAttribute(dcn_mma7_kernel,
                         cudaFuncAttributeMaxDynamicSharedMemorySize, SMEM_TOTAL);

    prep_weight<<<dim3(OO, KKT), CC>>>(weight);
    prep_nhwc<<<dim3(HWSZ / 32, CC / 32, BB), dim3(32, 8)>>>(inp);

    dim3 grid(HWSZ / TP, BB);   // (32, 8) = 256 CTAs
    dcn_mma7_kernel<<<grid, NT, SMEM_TOTAL>>>(offs, mask, bias, out);
}